// round 13
// baseline (speedup 1.0000x reference)
#include <cuda_runtime.h>
#include <cuda_fp16.h>
#include <cstdint>

#define DEVINL __device__ __forceinline__

namespace {

constexpr int HDIM = 128;
constexpr long long BROWS = 131072;
constexpr long long BH = BROWS * (long long)HDIM;
constexpr int THREADS = 512;
constexpr int M_TILE = 64;
constexpr int GRID = (int)(BROWS / M_TILE);  // 2048

// smem word (uint32) offsets
constexpr int SW_BIAS = 0;                      // 512 words fp32
constexpr int SW_A = 512;                       // packed A frags: 4bm*16ks*33 uint4
constexpr int A_WORDS = 4 * 16 * 33 * 4;        // 8448
constexpr int SW_RAW = SW_A + A_WORDS;          // 8960; raw A 64x256 fp32 (reused as B pair-3 slot)
constexpr int RAW_WORDS = 64 * 256;             // 16384
constexpr int SW_B = SW_RAW + RAW_WORDS;        // 25344; 3 pair-slots x 8192 words
constexpr int B_SLOT = 4096;                    // one k-step
constexpr int SMEM_WORDS = SW_B + 6 * B_SLOT;   // 49920
constexpr int SMEM_BYTES = SMEM_WORDS * 4;      // 199680 -> 1 CTA/SM

// Pre-packed weights, fragment order:
// word idx = ks*4096 + fq*128 + lane*4 + wq;  fq = g*8 + wN; wq = subn*2 + bsel
__device__ uint32_t g_wpack[16 * 32 * 128];     // 65536 words, 256 KB

DEVINL void cp16(uint32_t saddr, const void* gaddr) {
    asm volatile("cp.async.cg.shared.global [%0], [%1], 16;"
                 :: "r"(saddr), "l"(gaddr) : "memory");
}
DEVINL void cp_commit() { asm volatile("cp.async.commit_group;" ::: "memory"); }

DEVINL uint32_t packh2(float lo, float hi) {
    __half2 h = __floats2half2_rn(lo, hi);
    return *reinterpret_cast<uint32_t*>(&h);
}

DEVINL void mma16(float* d, const uint4& a, uint32_t b0, uint32_t b1) {
    asm volatile(
        "mma.sync.aligned.m16n8k16.row.col.f32.f16.f16.f32 "
        "{%0,%1,%2,%3}, {%4,%5,%6,%7}, {%8,%9}, {%0,%1,%2,%3};"
        : "+f"(d[0]), "+f"(d[1]), "+f"(d[2]), "+f"(d[3])
        : "r"(a.x), "r"(a.y), "r"(a.z), "r"(a.w), "r"(b0), "r"(b1));
}

DEVINL float sigf(float x) {
    return __fdividef(1.0f, 1.0f + __expf(-x));
}
DEVINL float tanhfast(float x) {
    return __fdividef(2.0f, 1.0f + __expf(-2.0f * x)) - 1.0f;
}

// 4-pair ring: pairs 0..2 in SW_B, pair 3 reuses the (dead) raw-A region.
DEVINL int pair_base(int p) {
    int q = p & 3;
    return (q < 3) ? (SW_B + q * 2 * B_SLOT) : SW_RAW;
}

// Packed A word index for fp16x2 word holding (r,k),(r,k+1), k even; r 0..63.
// Consumer reads uint4 at ((bm*16 + ks)*33 + lane), bm = r>>4 in 0..3.
DEVINL int widx(int r, int k) {
    int bm = r >> 4, rb = r & 15, ks = k >> 4, kr = k & 15;
    int lane_f = ((rb & 7) << 2) | ((kr & 7) >> 1);
    int q = ((kr >> 3) << 1) | (rb >> 3);
    return (((bm * 16 + ks) * 33 + lane_f) << 2) + q;
}

// ---- pre-pack: weights fp32 -> fp16x2 fragment-ordered image (256 KB) ----
__global__ void pack_weights(const float* __restrict__ wxi, const float* __restrict__ wxf,
                             const float* __restrict__ wxg, const float* __restrict__ wxo,
                             const float* __restrict__ whi, const float* __restrict__ whf,
                             const float* __restrict__ whg, const float* __restrict__ who) {
    const float* wx[4] = {wxi, wxf, wxg, wxo};
    const float* wh[4] = {whi, whf, whg, who};
    int idx = blockIdx.x * blockDim.x + threadIdx.x;  // 0..65535
    int wq = idx & 3;
    int lane = (idx >> 2) & 31;
    int fq = (idx >> 7) & 31;
    int ks = (idx >> 12) & 15;
    int g = fq >> 3, wN = fq & 7;
    int subn = wq >> 1, bsel = wq & 1;
    int n = wN * 16 + subn * 8 + (lane >> 2);
    int k0 = ks * 16 + 2 * (lane & 3) + bsel * 8;
    const float* w = (k0 < 128) ? wx[g] : wh[g];
    int kk = k0 & 127;
    float lo = w[(size_t)kk * HDIM + n];
    float hi = w[(size_t)(kk + 1) * HDIM + n];
    g_wpack[idx] = packh2(lo, hi);
}

// Issue cp.async group for raw A half ah (rows ah*32..ah*32+31), 32 KB.
DEVINL void issue_rawA(int ah, uint32_t smem_u32, int tid,
                       const float* __restrict__ x, const float* __restrict__ h,
                       long long row0) {
    const uint32_t dst = smem_u32 + (uint32_t)((SW_RAW + ah * 8192) * 4);
#pragma unroll
    for (int i = 0; i < 4; i++) {
        int l = i * THREADS + tid;  // line 0..2047 within half
        int r = ah * 32 + (l >> 6);
        int c = (l & 63) * 4;
        const float* gsrc = (c < 128) ? (x + (row0 + r) * HDIM + c)
                                      : (h + (row0 + r) * HDIM + (c - 128));
        cp16(dst + l * 16, gsrc);
    }
    cp_commit();
}

// Issue cp.async group for B k-step pair p (ks = 2p, 2p+1), 32 KB.
DEVINL void issue_Bpair(int p, uint32_t smem_u32, int tid) {
    const uint32_t dst = smem_u32 + (uint32_t)(pair_base(p) * 4);
    const uint32_t* src = g_wpack + p * 8192;
#pragma unroll
    for (int i = 0; i < 4; i++) {
        int l = i * THREADS + tid;  // line 0..2047
        cp16(dst + l * 16, src + l * 4);
    }
    cp_commit();
}

__global__ void __launch_bounds__(THREADS, 1)
lstm_kernel(const float* __restrict__ x, const float* __restrict__ hprev,
            const float* __restrict__ cprev,
            const float* __restrict__ bi, const float* __restrict__ bf,
            const float* __restrict__ bg, const float* __restrict__ bo,
            float* __restrict__ outh, float* __restrict__ outc, int writeC) {
    extern __shared__ float sm[];
    uint32_t* smw = reinterpret_cast<uint32_t*>(sm);
    const int tid = threadIdx.x;
    const int lane = tid & 31;
    const int wid = tid >> 5;
    const int wM = wid >> 3;  // 0..1 (32 rows each)
    const int wN = wid & 7;   // 0..7 (16 h-cols each)
    const long long row0 = (long long)blockIdx.x * M_TILE;
    const uint32_t smem_u32 = (uint32_t)__cvta_generic_to_shared(sm);

    // Prologue: raw A (2 groups) then 3 B pairs (pairs 0-2, slots in SW_B).
    issue_rawA(0, smem_u32, tid, x, hprev, row0);
    issue_rawA(1, smem_u32, tid, x, hprev, row0);
    issue_Bpair(0, smem_u32, tid);
    issue_Bpair(1, smem_u32, tid);
    issue_Bpair(2, smem_u32, tid);

    // biases [i|f|g|o] x 128
    {
        int g = tid >> 7, e = tid & 127;
        const float* bsrc = (g == 0) ? bi : (g == 1) ? bf : (g == 2) ? bg : bo;
        sm[SW_BIAS + tid] = bsrc[e];
    }

    float acc[2][8][4];
#pragma unroll
    for (int mi = 0; mi < 2; mi++)
#pragma unroll
        for (int f = 0; f < 8; f++)
#pragma unroll
            for (int q = 0; q < 4; q++) acc[mi][f][q] = 0.0f;

    // Wait for raw A (the 2 oldest groups; 3 B pairs may stay in flight).
    asm volatile("cp.async.wait_group 3;" ::: "memory");
    __syncthreads();

    // Convert all of A: 8192 fp16x2 words, 16 per thread.
#pragma unroll
    for (int j = 0; j < 16; j++) {
        int p = j * THREADS + tid;  // float2 index 0..8191
        int r = p >> 7;
        int kp = (p & 127) * 2;
        float2 f2 = *reinterpret_cast<const float2*>(sm + SW_RAW + r * 256 + kp);
        smw[SW_A + widx(r, kp)] = packh2(f2.x, f2.y);
    }
    __syncthreads();
    // From here the raw-A region is dead; it becomes B pair-ring slot 3.

    const uint4* apack = reinterpret_cast<const uint4*>(smw + SW_A);

#pragma unroll 1
    for (int p = 0; p < 8; p++) {
        // Wait for B pair p; countdown near the tail.
        if (p <= 5) {
            asm volatile("cp.async.wait_group 2;" ::: "memory");
        } else if (p == 6) {
            asm volatile("cp.async.wait_group 1;" ::: "memory");
        } else {
            asm volatile("cp.async.wait_group 0;" ::: "memory");
        }
        __syncthreads();
        // Writer targets pair (p+3) % 4 ring slot; reader uses p % 4 — disjoint.
        if (p + 3 < 8) issue_Bpair(p + 3, smem_u32, tid);

        const int pb = pair_base(p);
#pragma unroll
        for (int s = 0; s < 2; s++) {
            const int ks = p * 2 + s;
            uint4 a0 = apack[((wM * 2 + 0) * 16 + ks) * 33 + lane];
            uint4 a1 = apack[((wM * 2 + 1) * 16 + ks) * 33 + lane];
            const uint4* bp = reinterpret_cast<const uint4*>(smw + pb + s * B_SLOT);
#pragma unroll
            for (int g = 0; g < 4; g++) {
                uint4 bv = bp[(g * 8 + wN) * 32 + lane];
                mma16(acc[0][g * 2 + 0], a0, bv.x, bv.y);
                mma16(acc[0][g * 2 + 1], a0, bv.z, bv.w);
                mma16(acc[1][g * 2 + 0], a1, bv.x, bv.y);
                mma16(acc[1][g * 2 + 1], a1, bv.z, bv.w);
            }
        }
    }

    // Epilogue: warp owns h-cols [wN*16, wN*16+16), rows wM*32..+32; all gates.
    const float* bsm = sm + SW_BIAS;
#pragma unroll
    for (int mi = 0; mi < 2; mi++) {
#pragma unroll
        for (int rh = 0; rh < 2; rh++) {
            const long long m = row0 + wM * 32 + mi * 16 + (lane >> 2) + rh * 8;
#pragma unroll
            for (int subn = 0; subn < 2; subn++) {
                const int n = wN * 16 + subn * 8 + 2 * (lane & 3);
                float2 cp2 = *reinterpret_cast<const float2*>(cprev + m * HDIM + n);
                float hv[2], cv[2];
#pragma unroll
                for (int col = 0; col < 2; col++) {
                    float ai = acc[mi][0 * 2 + subn][rh * 2 + col] + bsm[n + col];
                    float af = acc[mi][1 * 2 + subn][rh * 2 + col] + bsm[128 + n + col];
                    float ag = acc[mi][2 * 2 + subn][rh * 2 + col] + bsm[256 + n + col];
                    float ao = acc[mi][3 * 2 + subn][rh * 2 + col] + bsm[384 + n + col];
                    float ig = sigf(ai);
                    float fg = sigf(af);
                    float og = sigf(ao);
                    float gg = tanhfast(ag);
                    float cpv = (col == 0) ? cp2.x : cp2.y;
                    float ct = fg * cpv + ig * gg;
                    cv[col] = ct;
                    hv[col] = og * tanhfast(ct);
                }
                *reinterpret_cast<float2*>(outh + m * HDIM + n) =
                    make_float2(hv[0], hv[1]);
                if (writeC) {
                    *reinterpret_cast<float2*>(outc + m * HDIM + n) =
                        make_float2(cv[0], cv[1]);
                }
            }
        }
    }
}

}  // namespace

extern "C" void kernel_launch(void* const* d_in, const int* in_sizes, int n_in,
                              void* d_out, int out_size) {
    (void)in_sizes; (void)n_in;
    cudaFuncSetAttribute(lstm_kernel, cudaFuncAttributeMaxDynamicSharedMemorySize,
                         SMEM_BYTES);
    const float* x     = (const float*)d_in[0];
    const float* hprev = (const float*)d_in[1];
    const float* cprev = (const float*)d_in[2];
    const float* wxi   = (const float*)d_in[3];
    const float* wxf   = (const float*)d_in[4];
    const float* wxg   = (const float*)d_in[5];
    const float* wxo   = (const float*)d_in[6];
    const float* whi   = (const float*)d_in[7];
    const float* whf   = (const float*)d_in[8];
    const float* whg   = (const float*)d_in[9];
    const float* who   = (const float*)d_in[10];
    const float* bi    = (const float*)d_in[11];
    const float* bf    = (const float*)d_in[12];
    const float* bg    = (const float*)d_in[13];
    const float* bo    = (const float*)d_in[14];

    float* outh = (float*)d_out;
    const long long need2 = 2LL * BH;
    int writeC = ((long long)out_size >= need2) ? 1 : 0;
    float* outc = outh + BH;

    pack_weights<<<256, 256>>>(wxi, wxf, wxg, wxo, whi, whf, whg, who);
    lstm_kernel<<<GRID, THREADS, SMEM_BYTES>>>(
        x, hprev, cprev, bi, bf, bg, bo, outh, outc, writeC);
}

// round 14
// speedup vs baseline: 1.2309x; 1.2309x over previous
#include <cuda_runtime.h>
#include <cuda_fp16.h>
#include <cstdint>

#define DEVINL __device__ __forceinline__

namespace {

constexpr int HDIM = 128;
constexpr long long BROWS = 131072;
constexpr long long BH = BROWS * (long long)HDIM;
constexpr int THREADS = 512;
constexpr int M_TILE = 64;
constexpr int GRID = (int)(BROWS / M_TILE);  // 2048

// smem word (uint32) offsets
constexpr int SW_BIAS = 0;                      // 512 words fp32
constexpr int SW_A = 512;                       // packed A frags: 4bm*16ks*33 uint4
constexpr int A_WORDS = 4 * 16 * 33 * 4;        // 8448
constexpr int SW_RAW = SW_A + A_WORDS;          // 8960; 4 slots x 1024 words fp32
constexpr int RAW_SLOT = 1024;
constexpr int SW_B = SW_RAW + 4 * RAW_SLOT;     // 13056; 6 ks-slots x 4096 words
constexpr int B_SLOT = 4096;
constexpr int SW_CP = SW_B + 6 * B_SLOT;        // 37632; cprev 64 x 132 fp32
constexpr int CP_PITCH = 132;
constexpr int SMEM_WORDS = SW_CP + 64 * CP_PITCH;  // 46080
constexpr int SMEM_BYTES = SMEM_WORDS * 4;      // 184320 -> 1 CTA/SM

// Pre-packed weights, fragment order:
// word idx = ks*4096 + fq*128 + lane*4 + wq;  fq = g*8 + wN; wq = subn*2 + bsel
__device__ uint32_t g_wpack[16 * 32 * 128];     // 65536 words, 256 KB

DEVINL void cp16(uint32_t saddr, const void* gaddr) {
    asm volatile("cp.async.cg.shared.global [%0], [%1], 16;"
                 :: "r"(saddr), "l"(gaddr) : "memory");
}
DEVINL void cp_commit() { asm volatile("cp.async.commit_group;" ::: "memory"); }

DEVINL uint32_t packh2(float lo, float hi) {
    __half2 h = __floats2half2_rn(lo, hi);
    return *reinterpret_cast<uint32_t*>(&h);
}

DEVINL void mma16(float* d, const uint4& a, uint32_t b0, uint32_t b1) {
    asm volatile(
        "mma.sync.aligned.m16n8k16.row.col.f32.f16.f16.f32 "
        "{%0,%1,%2,%3}, {%4,%5,%6,%7}, {%8,%9}, {%0,%1,%2,%3};"
        : "+f"(d[0]), "+f"(d[1]), "+f"(d[2]), "+f"(d[3])
        : "r"(a.x), "r"(a.y), "r"(a.z), "r"(a.w), "r"(b0), "r"(b1));
}

DEVINL float sigf(float x) {
    return __fdividef(1.0f, 1.0f + __expf(-x));
}
DEVINL float tanhfast(float x) {
    return __fdividef(2.0f, 1.0f + __expf(-2.0f * x)) - 1.0f;
}

// Packed A word index for fp16x2 word holding (r,k),(r,k+1), k even; r 0..63.
// Consumer reads uint4 at ((bm*16 + ks)*33 + lane), bm = r>>4 in 0..3.
DEVINL int widx(int r, int k) {
    int bm = r >> 4, rb = r & 15, ks = k >> 4, kr = k & 15;
    int lane_f = ((rb & 7) << 2) | ((kr & 7) >> 1);
    int q = ((kr >> 3) << 1) | (rb >> 3);
    return (((bm * 16 + ks) * 33 + lane_f) << 2) + q;
}

// ---- pre-pack: weights fp32 -> fp16x2 fragment-ordered image (256 KB) ----
__global__ void pack_weights(const float* __restrict__ wxi, const float* __restrict__ wxf,
                             const float* __restrict__ wxg, const float* __restrict__ wxo,
                             const float* __restrict__ whi, const float* __restrict__ whf,
                             const float* __restrict__ whg, const float* __restrict__ who) {
    const float* wx[4] = {wxi, wxf, wxg, wxo};
    const float* wh[4] = {whi, whf, whg, who};
    int idx = blockIdx.x * blockDim.x + threadIdx.x;  // 0..65535
    int wq = idx & 3;
    int lane = (idx >> 2) & 31;
    int fq = (idx >> 7) & 31;
    int ks = (idx >> 12) & 15;
    int g = fq >> 3, wN = fq & 7;
    int subn = wq >> 1, bsel = wq & 1;
    int n = wN * 16 + subn * 8 + (lane >> 2);
    int k0 = ks * 16 + 2 * (lane & 3) + bsel * 8;
    const float* w = (k0 < 128) ? wx[g] : wh[g];
    int kk = k0 & 127;
    float lo = w[(size_t)kk * HDIM + n];
    float hi = w[(size_t)(kk + 1) * HDIM + n];
    g_wpack[idx] = packh2(lo, hi);
}

// Issue cp.async group for k-step ks: B[ks] (16 KB) + raw A[ks] (4 KB fp32),
// optionally plus the full c_prev tile (32 KB) — attached once, at step 0.
DEVINL void issue_group(int ks, uint32_t smem_u32, int tid,
                        const float* __restrict__ x, const float* __restrict__ h,
                        const float* __restrict__ cprev, int with_cprev,
                        long long row0) {
    const uint32_t bdst = smem_u32 + (uint32_t)((SW_B + (ks % 6) * B_SLOT) * 4);
    const uint32_t* src = g_wpack + ks * 4096;
    cp16(bdst + tid * 16, src + tid * 4);
    cp16(bdst + (tid + 512) * 16, src + (tid + 512) * 4);
    if (tid < 256) {
        int r = tid >> 2, c4 = tid & 3;
        const float* gsrc =
            ((ks < 8) ? x : h) + (row0 + r) * HDIM + (ks & 7) * 16 + c4 * 4;
        cp16(smem_u32 + (uint32_t)((SW_RAW + (ks % 4) * RAW_SLOT) * 4) + tid * 16,
             gsrc);
    }
    if (with_cprev) {
#pragma unroll
        for (int i = 0; i < 4; i++) {
            int l = tid + i * THREADS;  // 16B line 0..2047
            int r = l >> 5, c = (l & 31) * 4;
            cp16(smem_u32 + (uint32_t)((SW_CP + r * CP_PITCH + c) * 4),
                 cprev + (row0 + r) * HDIM + c);
        }
    }
    cp_commit();
}

__global__ void __launch_bounds__(THREADS, 1)
lstm_kernel(const float* __restrict__ x, const float* __restrict__ hprev,
            const float* __restrict__ cprev,
            const float* __restrict__ bi, const float* __restrict__ bf,
            const float* __restrict__ bg, const float* __restrict__ bo,
            float* __restrict__ outh, float* __restrict__ outc, int writeC) {
    extern __shared__ float sm[];
    uint32_t* smw = reinterpret_cast<uint32_t*>(sm);
    const int tid = threadIdx.x;
    const int lane = tid & 31;
    const int wid = tid >> 5;
    const int wM = wid >> 3;  // 0..1 (32 rows each)
    const int wN = wid & 7;   // 0..7 (16 h-cols each)
    const long long row0 = (long long)blockIdx.x * M_TILE;
    const uint32_t smem_u32 = (uint32_t)__cvta_generic_to_shared(sm);

    // Prologue: 4 in-flight groups.
    issue_group(0, smem_u32, tid, x, hprev, cprev, 0, row0);
    issue_group(1, smem_u32, tid, x, hprev, cprev, 0, row0);
    issue_group(2, smem_u32, tid, x, hprev, cprev, 0, row0);
    issue_group(3, smem_u32, tid, x, hprev, cprev, 0, row0);

    // biases [i|f|g|o] x 128
    {
        int g = tid >> 7, e = tid & 127;
        const float* bsrc = (g == 0) ? bi : (g == 1) ? bf : (g == 2) ? bg : bo;
        sm[SW_BIAS + tid] = bsrc[e];
    }

    float acc[2][8][4];
#pragma unroll
    for (int mi = 0; mi < 2; mi++)
#pragma unroll
        for (int f = 0; f < 8; f++)
#pragma unroll
            for (int q = 0; q < 4; q++) acc[mi][f][q] = 0.0f;

    // Wait for group 0 (raw A[0]); convert packed A[0].
    asm volatile("cp.async.wait_group 3;" ::: "memory");
    __syncthreads();
    {
        const float* raw = sm + SW_RAW;  // slot 0
        float2 f2 = *reinterpret_cast<const float2*>(raw + tid * 2);
        int rr = tid >> 3, kw = tid & 7;
        smw[SW_A + widx(rr, kw * 2)] = packh2(f2.x, f2.y);
    }
    __syncthreads();

    const uint4* apack = reinterpret_cast<const uint4*>(smw + SW_A);

    // Mainloop: ONE barrier per ks; convert(ks+1) overlapped with compute(ks).
#define STEP(ks, W)                                                            \
    {                                                                          \
        asm volatile("cp.async.wait_group %0;" :: "n"(W) : "memory");          \
        __syncthreads();                                                       \
        if ((ks) + 4 < 16)                                                     \
            issue_group((ks) + 4, smem_u32, tid, x, hprev, cprev,              \
                        (ks) == 0 ? 1 : 0, row0);                              \
        if ((ks) + 1 < 16) {                                                   \
            const float* raw = sm + SW_RAW + (((ks) + 1) % 4) * RAW_SLOT;      \
            float2 f2 = *reinterpret_cast<const float2*>(raw + tid * 2);       \
            int rr = tid >> 3, kw = tid & 7;                                   \
            smw[SW_A + widx(rr, ((ks) + 1) * 16 + kw * 2)] =                   \
                packh2(f2.x, f2.y);                                            \
        }                                                                      \
        {                                                                      \
            uint4 a0 = apack[((wM * 2 + 0) * 16 + (ks)) * 33 + lane];          \
            uint4 a1 = apack[((wM * 2 + 1) * 16 + (ks)) * 33 + lane];          \
            const uint4* bp = reinterpret_cast<const uint4*>(                  \
                smw + SW_B + ((ks) % 6) * B_SLOT);                             \
            _Pragma("unroll")                                                  \
            for (int g = 0; g < 4; g++) {                                      \
                uint4 bv = bp[(g * 8 + wN) * 32 + lane];                       \
                mma16(acc[0][g * 2 + 0], a0, bv.x, bv.y);                      \
                mma16(acc[0][g * 2 + 1], a0, bv.z, bv.w);                      \
                mma16(acc[1][g * 2 + 0], a1, bv.x, bv.y);                      \
                mma16(acc[1][g * 2 + 1], a1, bv.z, bv.w);                      \
            }                                                                  \
        }                                                                      \
    }

    STEP(0, 2)  STEP(1, 2)  STEP(2, 2)  STEP(3, 2)
    STEP(4, 2)  STEP(5, 2)  STEP(6, 2)  STEP(7, 2)
    STEP(8, 2)  STEP(9, 2)  STEP(10, 2) STEP(11, 2)
    STEP(12, 2) STEP(13, 1) STEP(14, 0) STEP(15, 0)
#undef STEP

    // Epilogue: warp owns h-cols [wN*16, wN*16+16), rows wM*32..+32; all gates.
    // c_prev comes from smem (prefetched at step 0, completed long ago).
    const float* bsm = sm + SW_BIAS;
    const float* cpsm = sm + SW_CP;
#pragma unroll
    for (int mi = 0; mi < 2; mi++) {
#pragma unroll
        for (int rh = 0; rh < 2; rh++) {
            const int rloc = wM * 32 + mi * 16 + (lane >> 2) + rh * 8;
            const long long m = row0 + rloc;
#pragma unroll
            for (int subn = 0; subn < 2; subn++) {
                const int n = wN * 16 + subn * 8 + 2 * (lane & 3);
                float2 cp2 =
                    *reinterpret_cast<const float2*>(cpsm + rloc * CP_PITCH + n);
                float hv[2], cv[2];
#pragma unroll
                for (int col = 0; col < 2; col++) {
                    float ai = acc[mi][0 * 2 + subn][rh * 2 + col] + bsm[n + col];
                    float af = acc[mi][1 * 2 + subn][rh * 2 + col] + bsm[128 + n + col];
                    float ag = acc[mi][2 * 2 + subn][rh * 2 + col] + bsm[256 + n + col];
                    float ao = acc[mi][3 * 2 + subn][rh * 2 + col] + bsm[384 + n + col];
                    float ig = sigf(ai);
                    float fg = sigf(af);
                    float og = sigf(ao);
                    float gg = tanhfast(ag);
                    float cpv = (col == 0) ? cp2.x : cp2.y;
                    float ct = fg * cpv + ig * gg;
                    cv[col] = ct;
                    hv[col] = og * tanhfast(ct);
                }
                *reinterpret_cast<float2*>(outh + m * HDIM + n) =
                    make_float2(hv[0], hv[1]);
                if (writeC) {
                    *reinterpret_cast<float2*>(outc + m * HDIM + n) =
                        make_float2(cv[0], cv[1]);
                }
            }
        }
    }
}

}  // namespace

extern "C" void kernel_launch(void* const* d_in, const int* in_sizes, int n_in,
                              void* d_out, int out_size) {
    (void)in_sizes; (void)n_in;
    cudaFuncSetAttribute(lstm_kernel, cudaFuncAttributeMaxDynamicSharedMemorySize,
                         SMEM_BYTES);
    const float* x     = (const float*)d_in[0];
    const float* hprev = (const float*)d_in[1];
    const float* cprev = (const float*)d_in[2];
    const float* wxi   = (const float*)d_in[3];
    const float* wxf   = (const float*)d_in[4];
    const float* wxg   = (const float*)d_in[5];
    const float* wxo   = (const float*)d_in[6];
    const float* whi   = (const float*)d_in[7];
    const float* whf   = (const float*)d_in[8];
    const float* whg   = (const float*)d_in[9];
    const float* who   = (const float*)d_in[10];
    const float* bi    = (const float*)d_in[11];
    const float* bf    = (const float*)d_in[12];
    const float* bg    = (const float*)d_in[13];
    const float* bo    = (const float*)d_in[14];

    float* outh = (float*)d_out;
    const long long need2 = 2LL * BH;
    int writeC = ((long long)out_size >= need2) ? 1 : 0;
    float* outc = outh + BH;

    pack_weights<<<256, 256>>>(wxi, wxf, wxg, wxo, whi, whf, whg, who);
    lstm_kernel<<<GRID, THREADS, SMEM_BYTES>>>(
        x, hprev, cprev, bi, bf, bg, bo, outh, outc, writeC);
}